// round 14
// baseline (speedup 1.0000x reference)
#include <cuda_runtime.h>
#include <cuda_fp16.h>
#include <math.h>

#define N_NODES 100000
#define N_EDGES 3200000
#define FULLM 0xffffffffu
#define TB 256
#define EB ((N_EDGES + TB - 1) / TB)                  // edge blocks (12500)
#define G1B ((N_NODES + 7) / 8)                       // gemm1 warp blocks (12500)
#define CAP 64                                        // bin slots per node
#define OVF_CAP 32768

// ---------------- device scratch ----------------------------------------------
__device__ int    g_is64;
__device__ int    g_cnt[N_NODES];
__device__ int    g_bins[N_NODES * CAP];  // src ids, bins[d*64 + r]
__device__ int    g_ovf_cnt;
__device__ int    g_ovf_d[OVF_CAP];
__device__ int    g_ovf_s[OVF_CAP];
__device__ float  g_dinv[N_NODES];
__device__ __half g_H1[N_NODES * 64];   // layer-1 gather buf (128B rows)
__device__ __half g_H2[N_NODES * 32];   // layer-2 gather buf (64B rows)
__device__ __half g_H3[N_NODES * 16];   // layer-3 gather buf (32B rows)
__device__ float  g_H4[N_NODES * 8];    // layer-4 gather buf (32B rows, fp32)

// ---------------- init: zero cnt + ovf + dtype detect ---------------------------
__global__ __launch_bounds__(TB) void k_init(const void* ei) {
    int i = blockIdx.x * blockDim.x + threadIdx.x;
    if (i < N_NODES) g_cnt[i] = 0;
    if (blockIdx.x == 0) {
        __shared__ int any_nz;
        if (threadIdx.x == 0) { any_nz = 0; g_ovf_cnt = 0; }
        __syncthreads();
        const int* w = (const int*)ei;
        for (int k = threadIdx.x; k < 4096; k += blockDim.x)
            if (w[2 * k + 1] != 0) any_nz = 1;
        __syncthreads();
        if (threadIdx.x == 0) g_is64 = any_nz ? 0 : 1;
    }
}

// ---------------- count + direct bin fill ----------------------------------------
__global__ void k_count_fill(const void* __restrict__ ei) {
    int e = blockIdx.x * blockDim.x + threadIdx.x;
    if (e < N_EDGES) {
        int is64 = g_is64;
        int s, d;
        if (is64) {
            s = (int)((const long long*)ei)[e];
            d = (int)((const long long*)ei)[(long long)N_EDGES + e];
        } else {
            s = ((const int*)ei)[e];
            d = ((const int*)ei)[N_EDGES + e];
        }
        if ((unsigned)d < N_NODES) {
            int r = atomicAdd(&g_cnt[d], 1);
            if (r < CAP) {
                g_bins[d * CAP + r] = s;
            } else {
                int o = atomicAdd(&g_ovf_cnt, 1);
                if (o < OVF_CAP) { g_ovf_d[o] = d; g_ovf_s[o] = s; }
            }
        }
    }
}

// ---------------- gemm1 (warp per node) + dinv ------------------------------------
__global__ __launch_bounds__(TB) void k_gemm1(
    const float* __restrict__ x, const float* __restrict__ W)
{
    __shared__ float2 sW2[34 * 32];   // sW2[k*32+j] = W[k][2j..2j+1]
    for (int i = threadIdx.x; i < 34 * 32; i += blockDim.x) {
        int k = i >> 5, j = i & 31;
        sW2[i] = make_float2(W[k * 64 + 2 * j], W[k * 64 + 2 * j + 1]);
    }
    __syncthreads();
    int warp = blockIdx.x * 8 + (threadIdx.x >> 5);
    int lane = threadIdx.x & 31;
    if (warp >= N_NODES) return;
    const int node = warp;

    const float2* xr = (const float2*)(x + (size_t)node * 34);
    float2 xv = (lane < 17) ? xr[lane] : make_float2(0.f, 0.f);

    float a0 = 0.f, a1 = 0.f;
#pragma unroll
    for (int k = 0; k < 17; k++) {
        float x0 = __shfl_sync(FULLM, xv.x, k);
        float x1 = __shfl_sync(FULLM, xv.y, k);
        float2 w0 = sW2[(2 * k) * 32 + lane];
        float2 w1 = sW2[(2 * k + 1) * 32 + lane];
        a0 += x0 * w0.x + x1 * w1.x;
        a1 += x0 * w0.y + x1 * w1.y;
    }
    float dv = rsqrtf((float)g_cnt[node] + 1.0f);   // +1 self loop
    if (lane == 0) g_dinv[node] = dv;
    ((__half2*)g_H1)[(size_t)node * 32 + lane] =
        __floats2half2_rn(a0 * dv, a1 * dv);
}

// ---------------- F1: aggregate 64d (4-deep HADD2) + shfl-free GEMM 64->32 -------
__global__ __launch_bounds__(256) void k_f1(
    const float* __restrict__ b1, const float* __restrict__ W2)
{
    __shared__ __align__(16) float sWT[32 * 68];  // sWT[f*68+k] = W2[k][f] (padded)
    __shared__ __align__(16) float sh_h[8][64];   // per-warp h staging
    for (int i = threadIdx.x; i < 32 * 64; i += blockDim.x) {
        int f = i >> 6, k = i & 63;
        sWT[f * 68 + k] = W2[k * 32 + f];
    }
    __syncthreads();

    int wid  = threadIdx.x >> 5;
    int lane = threadIdx.x & 31;
    int warp = blockIdx.x * 8 + wid;
    if (warp >= N_NODES) return;
    const int node = warp;
    const __half2* t = (const __half2*)g_H1;

    float2 self = __half22float2(t[(size_t)node * 32 + lane]);
    float ax0 = self.x, ay0 = self.y, ax1 = 0.f, ay1 = 0.f;

    int deg = g_cnt[node];
    int m = min(deg, CAP);
    const int* bin = g_bins + node * CAP;
    int e0 = 0;
    for (; e0 + 32 <= m; e0 += 32) {
        int s = bin[e0 + lane];
#pragma unroll
        for (int j = 0; j < 32; j += 8) {        // 8 edges: two 4-deep fp16 trees
            int s0 = __shfl_sync(FULLM, s, j);
            int s1 = __shfl_sync(FULLM, s, j + 1);
            int s2 = __shfl_sync(FULLM, s, j + 2);
            int s3 = __shfl_sync(FULLM, s, j + 3);
            int s4 = __shfl_sync(FULLM, s, j + 4);
            int s5 = __shfl_sync(FULLM, s, j + 5);
            int s6 = __shfl_sync(FULLM, s, j + 6);
            int s7 = __shfl_sync(FULLM, s, j + 7);
            __half2 v0 = t[(size_t)s0 * 32 + lane];
            __half2 v1 = t[(size_t)s1 * 32 + lane];
            __half2 v2 = t[(size_t)s2 * 32 + lane];
            __half2 v3 = t[(size_t)s3 * 32 + lane];
            __half2 v4 = t[(size_t)s4 * 32 + lane];
            __half2 v5 = t[(size_t)s5 * 32 + lane];
            __half2 v6 = t[(size_t)s6 * 32 + lane];
            __half2 v7 = t[(size_t)s7 * 32 + lane];
            __half2 u0 = __hadd2(__hadd2(v0, v1), __hadd2(v2, v3));
            __half2 u1 = __hadd2(__hadd2(v4, v5), __hadd2(v6, v7));
            float2 p0 = __half22float2(u0);
            float2 p1 = __half22float2(u1);
            ax0 += p0.x; ay0 += p0.y;
            ax1 += p1.x; ay1 += p1.y;
        }
    }
    if (e0 < m) {
        int mm = m - e0;
        int s = (e0 + lane < m) ? bin[e0 + lane] : 0;
        for (int j = 0; j < mm; j++) {
            int sj = __shfl_sync(FULLM, s, j);
            float2 r = __half22float2(t[(size_t)sj * 32 + lane]);
            ax0 += r.x; ay0 += r.y;
        }
    }
    int L = g_ovf_cnt; if (L > OVF_CAP) L = OVF_CAP;
    for (int i = 0; i < L; i++) {
        if (g_ovf_d[i] == node) {
            float2 r = __half22float2(t[(size_t)g_ovf_s[i] * 32 + lane]);
            ax0 += r.x; ay0 += r.y;
        }
    }

    float d = g_dinv[node];
    float2 bv = ((const float2*)b1)[lane];
    float hx = tanhf(d * (ax0 + ax1) + bv.x);   // h1[2*lane]
    float hy = tanhf(d * (ay0 + ay1) + bv.y);   // h1[2*lane+1]

    // shfl-free GEMM 64->32: stage h in smem, read transposed weights
    ((float2*)sh_h[wid])[lane] = make_float2(hx, hy);
    __syncwarp();
    const float4* hv4 = (const float4*)sh_h[wid];
    const float4* wv4 = (const float4*)&sWT[lane * 68];
    float acc = 0.f;
#pragma unroll
    for (int kk = 0; kk < 16; kk++) {
        float4 h4 = hv4[kk];
        float4 w4 = wv4[kk];
        acc += h4.x * w4.x + h4.y * w4.y + h4.z * w4.z + h4.w * w4.w;
    }
    g_H2[(size_t)node * 32 + lane] = __float2half(acc * d);
}

// ---------------- F2: aggregate 32d (4-deep HADD2) + GEMM 32->16 -> H3 -----------
__global__ __launch_bounds__(256) void k_f2(
    const float* __restrict__ b2, const float* __restrict__ W3)
{
    __shared__ float sW[32 * 16];
    for (int i = threadIdx.x; i < 32 * 16; i += blockDim.x) sW[i] = W3[i];
    __syncthreads();

    int warp = (blockIdx.x * blockDim.x + threadIdx.x) >> 5;
    int lane = threadIdx.x & 31;
    if (warp >= N_NODES) return;
    const int node = warp;
    const __half2* t = (const __half2*)g_H2;
    int sub = lane >> 4;          // 2 subgroups
    int c   = lane & 15;

    float ax = 0.f, ay = 0.f, bx = 0.f, by = 0.f;
    if (sub == 0) {
        float2 s = __half22float2(t[(size_t)node * 16 + c]);
        ax = s.x; ay = s.y;
    }
    int deg = g_cnt[node];
    int m = min(deg, CAP);
    const int* bin = g_bins + node * CAP;
    int e = sub;
    for (; e + 14 < m; e += 16) {
        int s0 = bin[e];
        int s1 = bin[e + 2];
        int s2 = bin[e + 4];
        int s3 = bin[e + 6];
        int s4 = bin[e + 8];
        int s5 = bin[e + 10];
        int s6 = bin[e + 12];
        int s7 = bin[e + 14];
        __half2 v0 = t[(size_t)s0 * 16 + c];
        __half2 v1 = t[(size_t)s1 * 16 + c];
        __half2 v2 = t[(size_t)s2 * 16 + c];
        __half2 v3 = t[(size_t)s3 * 16 + c];
        __half2 v4 = t[(size_t)s4 * 16 + c];
        __half2 v5 = t[(size_t)s5 * 16 + c];
        __half2 v6 = t[(size_t)s6 * 16 + c];
        __half2 v7 = t[(size_t)s7 * 16 + c];
        __half2 u0 = __hadd2(__hadd2(v0, v1), __hadd2(v2, v3));
        __half2 u1 = __hadd2(__hadd2(v4, v5), __hadd2(v6, v7));
        float2 p0 = __half22float2(u0);
        float2 p1 = __half22float2(u1);
        ax += p0.x; ay += p0.y;
        bx += p1.x; by += p1.y;
    }
    for (; e < m; e += 2) {
        float2 r = __half22float2(t[(size_t)bin[e] * 16 + c]);
        ax += r.x; ay += r.y;
    }
    int L = g_ovf_cnt; if (L > OVF_CAP) L = OVF_CAP;
    for (int i = 0; i < L; i++) {
        if (g_ovf_d[i] == node && (i & 1) == sub) {
            float2 r = __half22float2(t[(size_t)g_ovf_s[i] * 16 + c]);
            ax += r.x; ay += r.y;
        }
    }
    ax += bx; ay += by;
    ax += __shfl_xor_sync(FULLM, ax, 16);
    ay += __shfl_xor_sync(FULLM, ay, 16);

    float d = g_dinv[node];
    float2 bv = ((const float2*)b2)[c];
    float hx = tanhf(d * ax + bv.x);    // h2[2c]
    float hy = tanhf(d * ay + bv.y);    // h2[2c+1]

    // GEMM 32->16: lanes 0..15 compute f = c
    float acc = 0.f;
#pragma unroll
    for (int k = 0; k < 16; k++) {
        float x0 = __shfl_sync(FULLM, hx, k);
        float x1 = __shfl_sync(FULLM, hy, k);
        acc += x0 * sW[(2 * k) * 16 + c] + x1 * sW[(2 * k + 1) * 16 + c];
    }
    if (sub == 0)
        g_H3[(size_t)node * 16 + c] = __float2half(acc * d);
}

// ---------------- F3: aggregate 16d (4-deep HADD2) + GEMM 16->8 -> H4 ------------
__global__ __launch_bounds__(256) void k_f3(
    const float* __restrict__ b3, const float* __restrict__ W4)
{
    __shared__ float sW[16 * 8];
    for (int i = threadIdx.x; i < 16 * 8; i += blockDim.x) sW[i] = W4[i];
    __syncthreads();

    int warp = (blockIdx.x * blockDim.x + threadIdx.x) >> 5;
    int lane = threadIdx.x & 31;
    if (warp >= N_NODES) return;
    const int node = warp;
    const __half2* t = (const __half2*)g_H3;
    int sub = lane >> 3;          // 4 subgroups
    int c   = lane & 7;

    float ax = 0.f, ay = 0.f, bx = 0.f, by = 0.f;
    if (sub == 0) {
        float2 s = __half22float2(t[(size_t)node * 8 + c]);
        ax = s.x; ay = s.y;
    }
    int deg = g_cnt[node];
    int m = min(deg, CAP);
    const int* bin = g_bins + node * CAP;
    int e = sub;
    for (; e + 28 < m; e += 32) {
        int s0 = bin[e];
        int s1 = bin[e + 4];
        int s2 = bin[e + 8];
        int s3 = bin[e + 12];
        int s4 = bin[e + 16];
        int s5 = bin[e + 20];
        int s6 = bin[e + 24];
        int s7 = bin[e + 28];
        __half2 v0 = t[(size_t)s0 * 8 + c];
        __half2 v1 = t[(size_t)s1 * 8 + c];
        __half2 v2 = t[(size_t)s2 * 8 + c];
        __half2 v3 = t[(size_t)s3 * 8 + c];
        __half2 v4 = t[(size_t)s4 * 8 + c];
        __half2 v5 = t[(size_t)s5 * 8 + c];
        __half2 v6 = t[(size_t)s6 * 8 + c];
        __half2 v7 = t[(size_t)s7 * 8 + c];
        __half2 u0 = __hadd2(__hadd2(v0, v1), __hadd2(v2, v3));
        __half2 u1 = __hadd2(__hadd2(v4, v5), __hadd2(v6, v7));
        float2 p0 = __half22float2(u0);
        float2 p1 = __half22float2(u1);
        ax += p0.x; ay += p0.y;
        bx += p1.x; by += p1.y;
    }
    for (; e < m; e += 4) {
        float2 r = __half22float2(t[(size_t)bin[e] * 8 + c]);
        ax += r.x; ay += r.y;
    }
    int L = g_ovf_cnt; if (L > OVF_CAP) L = OVF_CAP;
    for (int i = 0; i < L; i++) {
        if (g_ovf_d[i] == node && (i & 3) == sub) {
            float2 r = __half22float2(t[(size_t)g_ovf_s[i] * 8 + c]);
            ax += r.x; ay += r.y;
        }
    }
    ax += bx; ay += by;
    ax += __shfl_xor_sync(FULLM, ax, 8);
    ay += __shfl_xor_sync(FULLM, ay, 8);
    ax += __shfl_xor_sync(FULLM, ax, 16);
    ay += __shfl_xor_sync(FULLM, ay, 16);

    float d = g_dinv[node];
    float2 bv = ((const float2*)b3)[c];
    float hx = tanhf(d * ax + bv.x);    // h3[2c]
    float hy = tanhf(d * ay + bv.y);

    // GEMM 16->8: lanes 0..7 compute f = c
    float acc = 0.f;
#pragma unroll
    for (int k = 0; k < 8; k++) {
        float x0 = __shfl_sync(FULLM, hx, k);
        float x1 = __shfl_sync(FULLM, hy, k);
        acc += x0 * sW[(2 * k) * 8 + c] + x1 * sW[(2 * k + 1) * 8 + c];
    }
    if (sub == 0)
        g_H4[(size_t)node * 8 + c] = acc * d;
}

// ---------------- F4: aggregate 8d (fp32) + tanh + classifier -> d_out ----------
// d_out: [N*2 logits][N*8 hidden]
__global__ __launch_bounds__(256) void k_f4(
    const float* __restrict__ b4, const float* __restrict__ Wc,
    const float* __restrict__ bc, float* __restrict__ dout)
{
    int warp = (blockIdx.x * blockDim.x + threadIdx.x) >> 5;
    int lane = threadIdx.x & 31;
    if (warp >= N_NODES) return;
    const int node = warp;
    const float2* t = (const float2*)g_H4;
    int sub = lane >> 2;          // 8 subgroups
    int c   = lane & 3;

    float ax = 0.f, ay = 0.f, bx = 0.f, by = 0.f;
    if (sub == 0) {
        float2 s = t[(size_t)node * 4 + c];
        ax = s.x; ay = s.y;
    }
    int deg = g_cnt[node];
    int m = min(deg, CAP);
    const int* bin = g_bins + node * CAP;
    int e = sub;
    for (; e + 24 < m; e += 32) {
        int s0 = bin[e];
        int s1 = bin[e + 8];
        int s2 = bin[e + 16];
        int s3 = bin[e + 24];
        float2 r0 = t[(size_t)s0 * 4 + c];
        float2 r1 = t[(size_t)s1 * 4 + c];
        float2 r2 = t[(size_t)s2 * 4 + c];
        float2 r3 = t[(size_t)s3 * 4 + c];
        ax += r0.x; ay += r0.y;
        bx += r1.x; by += r1.y;
        ax += r2.x; ay += r2.y;
        bx += r3.x; by += r3.y;
    }
    for (; e < m; e += 8) {
        float2 r = t[(size_t)bin[e] * 4 + c];
        ax += r.x; ay += r.y;
    }
    int L = g_ovf_cnt; if (L > OVF_CAP) L = OVF_CAP;
    for (int i = 0; i < L; i++) {
        if (g_ovf_d[i] == node && (i & 7) == sub) {
            float2 r = t[(size_t)g_ovf_s[i] * 4 + c];
            ax += r.x; ay += r.y;
        }
    }
    ax += bx; ay += by;
    ax += __shfl_xor_sync(FULLM, ax, 4);
    ay += __shfl_xor_sync(FULLM, ay, 4);
    ax += __shfl_xor_sync(FULLM, ax, 8);
    ay += __shfl_xor_sync(FULLM, ay, 8);
    ax += __shfl_xor_sync(FULLM, ax, 16);
    ay += __shfl_xor_sync(FULLM, ay, 16);

    float d = g_dinv[node];
    float hx = tanhf(d * ax + b4[2 * c]);      // h4[2c]
    float hy = tanhf(d * ay + b4[2 * c + 1]);  // h4[2c+1]

    float p0 = hx * Wc[(2 * c) * 2 + 0] + hy * Wc[(2 * c + 1) * 2 + 0];
    float p1 = hx * Wc[(2 * c) * 2 + 1] + hy * Wc[(2 * c + 1) * 2 + 1];
    p0 += __shfl_xor_sync(FULLM, p0, 1);
    p1 += __shfl_xor_sync(FULLM, p1, 1);
    p0 += __shfl_xor_sync(FULLM, p0, 2);
    p1 += __shfl_xor_sync(FULLM, p1, 2);

    if (sub == 0) {
        float2* dh = (float2*)(dout + (size_t)2 * N_NODES);
        dh[(size_t)node * 4 + c] = make_float2(hx, hy);
        if (c == 0) {
            dout[(size_t)node * 2 + 0] = p0 + bc[0];
            dout[(size_t)node * 2 + 1] = p1 + bc[1];
        }
    }
}

// ---------------- launcher --------------------------------------------------------
extern "C" void kernel_launch(void* const* d_in, const int* in_sizes, int n_in,
                              void* d_out, int out_size)
{
    const float* x  = (const float*)d_in[0];
    const void*  ei = d_in[1];
    const float* W1 = (const float*)d_in[2];
    const float* b1 = (const float*)d_in[3];
    const float* W2 = (const float*)d_in[4];
    const float* b2 = (const float*)d_in[5];
    const float* W3 = (const float*)d_in[6];
    const float* b3 = (const float*)d_in[7];
    const float* W4 = (const float*)d_in[8];
    const float* b4 = (const float*)d_in[9];
    const float* Wc = (const float*)d_in[10];
    const float* bc = (const float*)d_in[11];
    float* out = (float*)d_out;

    const int nb = (N_NODES + TB - 1) / TB;
    const int wb = (N_NODES * 32 + TB - 1) / TB;  // one warp per node

    k_init<<<nb, TB>>>(ei);            // 0
    k_count_fill<<<EB, TB>>>(ei);      // 1
    k_gemm1<<<G1B, TB>>>(x, W1);       // 2
    k_f1<<<G1B, TB>>>(b1, W2);         // 3  (profiled)
    k_f2<<<wb, TB>>>(b2, W3);          // 4
    k_f3<<<wb, TB>>>(b3, W4);          // 5
    k_f4<<<wb, TB>>>(b4, Wc, bc, out); // 6
}

// round 15
// speedup vs baseline: 1.2021x; 1.2021x over previous
#include <cuda_runtime.h>
#include <cuda_fp16.h>
#include <math.h>

#define N_NODES 100000
#define N_EDGES 3200000
#define FULLM 0xffffffffu
#define TB 256
#define EB ((N_EDGES + TB - 1) / TB)                  // edge blocks (12500)
#define G1B ((N_NODES + 7) / 8)                       // warp-per-node blocks (12500)
#define CAP 64                                        // bin slots per node
#define OVF_CAP 32768

// ---------------- device scratch ----------------------------------------------
__device__ int    g_is64;
__device__ int    g_cnt[N_NODES];
__device__ int    g_bins[N_NODES * CAP];  // src ids, bins[d*64 + r]
__device__ int    g_ovf_cnt;
__device__ int    g_ovf_d[OVF_CAP];
__device__ int    g_ovf_s[OVF_CAP];
__device__ float  g_dinv[N_NODES];
__device__ __half g_H1[N_NODES * 64];   // layer-1 gather buf (128B rows)
__device__ __half g_H2[N_NODES * 32];   // layer-2 gather buf (64B rows)
__device__ __half g_H3[N_NODES * 16];   // layer-3 gather buf (32B rows)
__device__ float  g_H4[N_NODES * 8];    // layer-4 gather buf (32B rows, fp32)

// ---------------- init: zero cnt + ovf + dtype detect ---------------------------
__global__ __launch_bounds__(TB) void k_init(const void* ei) {
    int i = blockIdx.x * blockDim.x + threadIdx.x;
    if (i < N_NODES) g_cnt[i] = 0;
    if (blockIdx.x == 0) {
        __shared__ int any_nz;
        if (threadIdx.x == 0) { any_nz = 0; g_ovf_cnt = 0; }
        __syncthreads();
        const int* w = (const int*)ei;
        for (int k = threadIdx.x; k < 4096; k += blockDim.x)
            if (w[2 * k + 1] != 0) any_nz = 1;
        __syncthreads();
        if (threadIdx.x == 0) g_is64 = any_nz ? 0 : 1;
    }
}

// ---------------- fused: count + bin fill  ||  unscaled gemm1 --------------------
// blocks [0, EB): count/fill. blocks [EB, EB+G1B): H1 = half(x @ W1) (no dinv yet)
__global__ __launch_bounds__(TB) void k_count_gemm1(
    const void* __restrict__ ei, const float* __restrict__ x,
    const float* __restrict__ W)
{
    __shared__ float2 sW2[34 * 32];   // sW2[k*32+j] = W[k][2j..2j+1]
    if (blockIdx.x < EB) {
        int e = blockIdx.x * TB + threadIdx.x;
        if (e < N_EDGES) {
            int is64 = g_is64;
            int s, d;
            if (is64) {
                s = (int)((const long long*)ei)[e];
                d = (int)((const long long*)ei)[(long long)N_EDGES + e];
            } else {
                s = ((const int*)ei)[e];
                d = ((const int*)ei)[N_EDGES + e];
            }
            if ((unsigned)d < N_NODES) {
                int r = atomicAdd(&g_cnt[d], 1);
                if (r < CAP) {
                    g_bins[d * CAP + r] = s;
                } else {
                    int o = atomicAdd(&g_ovf_cnt, 1);
                    if (o < OVF_CAP) { g_ovf_d[o] = d; g_ovf_s[o] = s; }
                }
            }
        }
    } else {
        for (int i = threadIdx.x; i < 34 * 32; i += blockDim.x) {
            int k = i >> 5, j = i & 31;
            sW2[i] = make_float2(W[k * 64 + 2 * j], W[k * 64 + 2 * j + 1]);
        }
        __syncthreads();
        int warp = (blockIdx.x - EB) * 8 + (threadIdx.x >> 5);
        int lane = threadIdx.x & 31;
        if (warp >= N_NODES) return;
        const int node = warp;

        const float2* xr = (const float2*)(x + (size_t)node * 34);
        float2 xv = (lane < 17) ? xr[lane] : make_float2(0.f, 0.f);

        float a0 = 0.f, a1 = 0.f;
#pragma unroll
        for (int k = 0; k < 17; k++) {
            float x0 = __shfl_sync(FULLM, xv.x, k);
            float x1 = __shfl_sync(FULLM, xv.y, k);
            float2 w0 = sW2[(2 * k) * 32 + lane];
            float2 w1 = sW2[(2 * k + 1) * 32 + lane];
            a0 += x0 * w0.x + x1 * w1.x;
            a1 += x0 * w0.y + x1 * w1.y;
        }
        ((__half2*)g_H1)[(size_t)node * 32 + lane] = __floats2half2_rn(a0, a1);
    }
}

// ---------------- finalize: dinv + scale H1 in place -----------------------------
__global__ __launch_bounds__(TB) void k_finalize() {
    int idx = blockIdx.x * blockDim.x + threadIdx.x;   // over N*32 half2 elems
    if (idx >= N_NODES * 32) return;
    int node = idx >> 5;
    float dv = rsqrtf((float)g_cnt[node] + 1.0f);      // +1 self loop
    if ((idx & 31) == 0) g_dinv[node] = dv;
    __half2* h = (__half2*)g_H1;
    float2 v = __half22float2(h[idx]);
    h[idx] = __floats2half2_rn(v.x * dv, v.y * dv);
}

// ---------------- F1: aggregate 64d (4-deep HADD2) + GEMM 64->32 -> H2 -----------
__global__ __launch_bounds__(256) void k_f1(
    const float* __restrict__ b1, const float* __restrict__ W2)
{
    __shared__ float2 sW[32 * 32];   // sW[k*32+f] = (W2[2k][f], W2[2k+1][f]) 8KB
    for (int i = threadIdx.x; i < 32 * 32; i += blockDim.x) {
        int k = i >> 5, f = i & 31;
        sW[i] = make_float2(W2[(2 * k) * 32 + f], W2[(2 * k + 1) * 32 + f]);
    }
    __syncthreads();

    int warp = (blockIdx.x * blockDim.x + threadIdx.x) >> 5;
    int lane = threadIdx.x & 31;
    if (warp >= N_NODES) return;
    const int node = warp;
    const __half2* t = (const __half2*)g_H1;

    float2 self = __half22float2(t[(size_t)node * 32 + lane]);
    float ax0 = self.x, ay0 = self.y, ax1 = 0.f, ay1 = 0.f;

    int deg = g_cnt[node];
    int m = min(deg, CAP);
    const int* bin = g_bins + node * CAP;
    int e0 = 0;
    for (; e0 + 32 <= m; e0 += 32) {
        int s = bin[e0 + lane];
#pragma unroll
        for (int j = 0; j < 32; j += 8) {        // 8 edges: two 4-deep fp16 trees
            int s0 = __shfl_sync(FULLM, s, j);
            int s1 = __shfl_sync(FULLM, s, j + 1);
            int s2 = __shfl_sync(FULLM, s, j + 2);
            int s3 = __shfl_sync(FULLM, s, j + 3);
            int s4 = __shfl_sync(FULLM, s, j + 4);
            int s5 = __shfl_sync(FULLM, s, j + 5);
            int s6 = __shfl_sync(FULLM, s, j + 6);
            int s7 = __shfl_sync(FULLM, s, j + 7);
            __half2 v0 = t[(size_t)s0 * 32 + lane];
            __half2 v1 = t[(size_t)s1 * 32 + lane];
            __half2 v2 = t[(size_t)s2 * 32 + lane];
            __half2 v3 = t[(size_t)s3 * 32 + lane];
            __half2 v4 = t[(size_t)s4 * 32 + lane];
            __half2 v5 = t[(size_t)s5 * 32 + lane];
            __half2 v6 = t[(size_t)s6 * 32 + lane];
            __half2 v7 = t[(size_t)s7 * 32 + lane];
            __half2 u0 = __hadd2(__hadd2(v0, v1), __hadd2(v2, v3));
            __half2 u1 = __hadd2(__hadd2(v4, v5), __hadd2(v6, v7));
            float2 p0 = __half22float2(u0);
            float2 p1 = __half22float2(u1);
            ax0 += p0.x; ay0 += p0.y;
            ax1 += p1.x; ay1 += p1.y;
        }
    }
    if (e0 < m) {
        int mm = m - e0;
        int s = (e0 + lane < m) ? bin[e0 + lane] : 0;
        for (int j = 0; j < mm; j++) {
            int sj = __shfl_sync(FULLM, s, j);
            float2 r = __half22float2(t[(size_t)sj * 32 + lane]);
            ax0 += r.x; ay0 += r.y;
        }
    }
    int L = g_ovf_cnt; if (L > OVF_CAP) L = OVF_CAP;
    for (int i = 0; i < L; i++) {
        if (g_ovf_d[i] == node) {
            float2 r = __half22float2(t[(size_t)g_ovf_s[i] * 32 + lane]);
            ax0 += r.x; ay0 += r.y;
        }
    }

    float d = g_dinv[node];
    float2 bv = ((const float2*)b1)[lane];
    float hx = tanhf(d * (ax0 + ax1) + bv.x);   // h1[2*lane]
    float hy = tanhf(d * (ay0 + ay1) + bv.y);   // h1[2*lane+1]

    // GEMM 64->32 (packed float2 weights, shfl broadcast — R13 epilogue)
    float acc = 0.f;
#pragma unroll
    for (int k = 0; k < 32; k++) {
        float x0 = __shfl_sync(FULLM, hx, k);
        float x1 = __shfl_sync(FULLM, hy, k);
        float2 w = sW[k * 32 + lane];
        acc += x0 * w.x + x1 * w.y;
    }
    g_H2[(size_t)node * 32 + lane] = __float2half(acc * d);
}

// ---------------- F2: aggregate 32d (4-deep HADD2) + GEMM 32->16 -> H3 -----------
__global__ __launch_bounds__(256) void k_f2(
    const float* __restrict__ b2, const float* __restrict__ W3)
{
    __shared__ float sW[32 * 16];
    for (int i = threadIdx.x; i < 32 * 16; i += blockDim.x) sW[i] = W3[i];
    __syncthreads();

    int warp = (blockIdx.x * blockDim.x + threadIdx.x) >> 5;
    int lane = threadIdx.x & 31;
    if (warp >= N_NODES) return;
    const int node = warp;
    const __half2* t = (const __half2*)g_H2;
    int sub = lane >> 4;          // 2 subgroups
    int c   = lane & 15;

    float ax = 0.f, ay = 0.f, bx = 0.f, by = 0.f;
    if (sub == 0) {
        float2 s = __half22float2(t[(size_t)node * 16 + c]);
        ax = s.x; ay = s.y;
    }
    int deg = g_cnt[node];
    int m = min(deg, CAP);
    const int* bin = g_bins + node * CAP;
    int e = sub;
    for (; e + 14 < m; e += 16) {
        int s0 = bin[e];
        int s1 = bin[e + 2];
        int s2 = bin[e + 4];
        int s3 = bin[e + 6];
        int s4 = bin[e + 8];
        int s5 = bin[e + 10];
        int s6 = bin[e + 12];
        int s7 = bin[e + 14];
        __half2 v0 = t[(size_t)s0 * 16 + c];
        __half2 v1 = t[(size_t)s1 * 16 + c];
        __half2 v2 = t[(size_t)s2 * 16 + c];
        __half2 v3 = t[(size_t)s3 * 16 + c];
        __half2 v4 = t[(size_t)s4 * 16 + c];
        __half2 v5 = t[(size_t)s5 * 16 + c];
        __half2 v6 = t[(size_t)s6 * 16 + c];
        __half2 v7 = t[(size_t)s7 * 16 + c];
        __half2 u0 = __hadd2(__hadd2(v0, v1), __hadd2(v2, v3));
        __half2 u1 = __hadd2(__hadd2(v4, v5), __hadd2(v6, v7));
        float2 p0 = __half22float2(u0);
        float2 p1 = __half22float2(u1);
        ax += p0.x; ay += p0.y;
        bx += p1.x; by += p1.y;
    }
    for (; e < m; e += 2) {
        float2 r = __half22float2(t[(size_t)bin[e] * 16 + c]);
        ax += r.x; ay += r.y;
    }
    int L = g_ovf_cnt; if (L > OVF_CAP) L = OVF_CAP;
    for (int i = 0; i < L; i++) {
        if (g_ovf_d[i] == node && (i & 1) == sub) {
            float2 r = __half22float2(t[(size_t)g_ovf_s[i] * 16 + c]);
            ax += r.x; ay += r.y;
        }
    }
    ax += bx; ay += by;
    ax += __shfl_xor_sync(FULLM, ax, 16);
    ay += __shfl_xor_sync(FULLM, ay, 16);

    float d = g_dinv[node];
    float2 bv = ((const float2*)b2)[c];
    float hx = tanhf(d * ax + bv.x);    // h2[2c]
    float hy = tanhf(d * ay + bv.y);    // h2[2c+1]

    // GEMM 32->16: lanes 0..15 compute f = c
    float acc = 0.f;
#pragma unroll
    for (int k = 0; k < 16; k++) {
        float x0 = __shfl_sync(FULLM, hx, k);
        float x1 = __shfl_sync(FULLM, hy, k);
        acc += x0 * sW[(2 * k) * 16 + c] + x1 * sW[(2 * k + 1) * 16 + c];
    }
    if (sub == 0)
        g_H3[(size_t)node * 16 + c] = __float2half(acc * d);
}

// ---------------- F3: aggregate 16d (4-deep HADD2) + GEMM 16->8 -> H4 ------------
__global__ __launch_bounds__(256) void k_f3(
    const float* __restrict__ b3, const float* __restrict__ W4)
{
    __shared__ float sW[16 * 8];
    for (int i = threadIdx.x; i < 16 * 8; i += blockDim.x) sW[i] = W4[i];
    __syncthreads();

    int warp = (blockIdx.x * blockDim.x + threadIdx.x) >> 5;
    int lane = threadIdx.x & 31;
    if (warp >= N_NODES) return;
    const int node = warp;
    const __half2* t = (const __half2*)g_H3;
    int sub = lane >> 3;          // 4 subgroups
    int c   = lane & 7;

    float ax = 0.f, ay = 0.f, bx = 0.f, by = 0.f;
    if (sub == 0) {
        float2 s = __half22float2(t[(size_t)node * 8 + c]);
        ax = s.x; ay = s.y;
    }
    int deg = g_cnt[node];
    int m = min(deg, CAP);
    const int* bin = g_bins + node * CAP;
    int e = sub;
    for (; e + 28 < m; e += 32) {
        int s0 = bin[e];
        int s1 = bin[e + 4];
        int s2 = bin[e + 8];
        int s3 = bin[e + 12];
        int s4 = bin[e + 16];
        int s5 = bin[e + 20];
        int s6 = bin[e + 24];
        int s7 = bin[e + 28];
        __half2 v0 = t[(size_t)s0 * 8 + c];
        __half2 v1 = t[(size_t)s1 * 8 + c];
        __half2 v2 = t[(size_t)s2 * 8 + c];
        __half2 v3 = t[(size_t)s3 * 8 + c];
        __half2 v4 = t[(size_t)s4 * 8 + c];
        __half2 v5 = t[(size_t)s5 * 8 + c];
        __half2 v6 = t[(size_t)s6 * 8 + c];
        __half2 v7 = t[(size_t)s7 * 8 + c];
        __half2 u0 = __hadd2(__hadd2(v0, v1), __hadd2(v2, v3));
        __half2 u1 = __hadd2(__hadd2(v4, v5), __hadd2(v6, v7));
        float2 p0 = __half22float2(u0);
        float2 p1 = __half22float2(u1);
        ax += p0.x; ay += p0.y;
        bx += p1.x; by += p1.y;
    }
    for (; e < m; e += 4) {
        float2 r = __half22float2(t[(size_t)bin[e] * 8 + c]);
        ax += r.x; ay += r.y;
    }
    int L = g_ovf_cnt; if (L > OVF_CAP) L = OVF_CAP;
    for (int i = 0; i < L; i++) {
        if (g_ovf_d[i] == node && (i & 3) == sub) {
            float2 r = __half22float2(t[(size_t)g_ovf_s[i] * 8 + c]);
            ax += r.x; ay += r.y;
        }
    }
    ax += bx; ay += by;
    ax += __shfl_xor_sync(FULLM, ax, 8);
    ay += __shfl_xor_sync(FULLM, ay, 8);
    ax += __shfl_xor_sync(FULLM, ax, 16);
    ay += __shfl_xor_sync(FULLM, ay, 16);

    float d = g_dinv[node];
    float2 bv = ((const float2*)b3)[c];
    float hx = tanhf(d * ax + bv.x);    // h3[2c]
    float hy = tanhf(d * ay + bv.y);

    // GEMM 16->8: lanes 0..7 compute f = c
    float acc = 0.f;
#pragma unroll
    for (int k = 0; k < 8; k++) {
        float x0 = __shfl_sync(FULLM, hx, k);
        float x1 = __shfl_sync(FULLM, hy, k);
        acc += x0 * sW[(2 * k) * 8 + c] + x1 * sW[(2 * k + 1) * 8 + c];
    }
    if (sub == 0)
        g_H4[(size_t)node * 8 + c] = acc * d;
}

// ---------------- F4: aggregate 8d (fp32) + tanh + classifier -> d_out ----------
// d_out: [N*2 logits][N*8 hidden]
__global__ __launch_bounds__(256) void k_f4(
    const float* __restrict__ b4, const float* __restrict__ Wc,
    const float* __restrict__ bc, float* __restrict__ dout)
{
    int warp = (blockIdx.x * blockDim.x + threadIdx.x) >> 5;
    int lane = threadIdx.x & 31;
    if (warp >= N_NODES) return;
    const int node = warp;
    const float2* t = (const float2*)g_H4;
    int sub = lane >> 2;          // 8 subgroups
    int c   = lane & 3;

    float ax = 0.f, ay = 0.f, bx = 0.f, by = 0.f;
    if (sub == 0) {
        float2 s = t[(size_t)node * 4 + c];
        ax = s.x; ay = s.y;
    }
    int deg = g_cnt[node];
    int m = min(deg, CAP);
    const int* bin = g_bins + node * CAP;
    int e = sub;
    for (; e + 24 < m; e += 32) {
        int s0 = bin[e];
        int s1 = bin[e + 8];
        int s2 = bin[e + 16];
        int s3 = bin[e + 24];
        float2 r0 = t[(size_t)s0 * 4 + c];
        float2 r1 = t[(size_t)s1 * 4 + c];
        float2 r2 = t[(size_t)s2 * 4 + c];
        float2 r3 = t[(size_t)s3 * 4 + c];
        ax += r0.x; ay += r0.y;
        bx += r1.x; by += r1.y;
        ax += r2.x; ay += r2.y;
        bx += r3.x; by += r3.y;
    }
    for (; e < m; e += 8) {
        float2 r = t[(size_t)bin[e] * 4 + c];
        ax += r.x; ay += r.y;
    }
    int L = g_ovf_cnt; if (L > OVF_CAP) L = OVF_CAP;
    for (int i = 0; i < L; i++) {
        if (g_ovf_d[i] == node && (i & 7) == sub) {
            float2 r = t[(size_t)g_ovf_s[i] * 4 + c];
            ax += r.x; ay += r.y;
        }
    }
    ax += bx; ay += by;
    ax += __shfl_xor_sync(FULLM, ax, 4);
    ay += __shfl_xor_sync(FULLM, ay, 4);
    ax += __shfl_xor_sync(FULLM, ax, 8);
    ay += __shfl_xor_sync(FULLM, ay, 8);
    ax += __shfl_xor_sync(FULLM, ax, 16);
    ay += __shfl_xor_sync(FULLM, ay, 16);

    float d = g_dinv[node];
    float hx = tanhf(d * ax + b4[2 * c]);      // h4[2c]
    float hy = tanhf(d * ay + b4[2 * c + 1]);  // h4[2c+1]

    float p0 = hx * Wc[(2 * c) * 2 + 0] + hy * Wc[(2 * c + 1) * 2 + 0];
    float p1 = hx * Wc[(2 * c) * 2 + 1] + hy * Wc[(2 * c + 1) * 2 + 1];
    p0 += __shfl_xor_sync(FULLM, p0, 1);
    p1 += __shfl_xor_sync(FULLM, p1, 1);
    p0 += __shfl_xor_sync(FULLM, p0, 2);
    p1 += __shfl_xor_sync(FULLM, p1, 2);

    if (sub == 0) {
        float2* dh = (float2*)(dout + (size_t)2 * N_NODES);
        dh[(size_t)node * 4 + c] = make_float2(hx, hy);
        if (c == 0) {
            dout[(size_t)node * 2 + 0] = p0 + bc[0];
            dout[(size_t)node * 2 + 1] = p1 + bc[1];
        }
    }
}

// ---------------- launcher --------------------------------------------------------
extern "C" void kernel_launch(void* const* d_in, const int* in_sizes, int n_in,
                              void* d_out, int out_size)
{
    const float* x  = (const float*)d_in[0];
    const void*  ei = d_in[1];
    const float* W1 = (const float*)d_in[2];
    const float* b1 = (const float*)d_in[3];
    const float* W2 = (const float*)d_in[4];
    const float* b2 = (const float*)d_in[5];
    const float* W3 = (const float*)d_in[6];
    const float* b3 = (const float*)d_in[7];
    const float* W4 = (const float*)d_in[8];
    const float* b4 = (const float*)d_in[9];
    const float* Wc = (const float*)d_in[10];
    const float* bc = (const float*)d_in[11];
    float* out = (float*)d_out;

    const int nb = (N_NODES + TB - 1) / TB;
    const int wb = (N_NODES * 32 + TB - 1) / TB;  // one warp per node

    k_init<<<nb, TB>>>(ei);                        // 0
    k_count_gemm1<<<EB + G1B, TB>>>(ei, x, W1);    // 1  (count/fill || unscaled gemm1)
    k_finalize<<<G1B, TB>>>();                     // 2  (dinv + scale H1)
    k_f1<<<wb, TB>>>(b1, W2);                      // 3  (profiled)
    k_f2<<<wb, TB>>>(b2, W3);                      // 4
    k_f3<<<wb, TB>>>(b3, W4);                      // 5
    k_f4<<<wb, TB>>>(b4, Wc, bc, out);             // 6
}

// round 16
// speedup vs baseline: 1.2375x; 1.0294x over previous
#include <cuda_runtime.h>
#include <cuda_fp16.h>
#include <math.h>

#define N_NODES 100000
#define N_EDGES 3200000
#define FULLM 0xffffffffu
#define TB 256
#define EB ((N_EDGES + TB - 1) / TB)                  // edge blocks (12500)
#define G1B ((N_NODES + 7) / 8)                       // warp-per-node blocks (12500)
#define CAP 64                                        // bin slots per node
#define OVF_CAP 32768

// ---------------- device scratch ----------------------------------------------
__device__ int    g_is64;
__device__ int    g_cnt[N_NODES];
__device__ int    g_bins[N_NODES * CAP];  // src ids, bins[d*64 + r]
__device__ int    g_ovf_cnt;
__device__ int    g_ovf_d[OVF_CAP];
__device__ int    g_ovf_s[OVF_CAP];
__device__ float  g_dinv[N_NODES];
__device__ __half g_H1[N_NODES * 64];   // layer-1 gather buf (128B rows)
__device__ __half g_H2[N_NODES * 32];   // layer-2 gather buf (64B rows)
__device__ __half g_H3[N_NODES * 16];   // layer-3 gather buf (32B rows)
__device__ float  g_H4[N_NODES * 8];    // layer-4 gather buf (32B rows, fp32)

// ---------------- init: zero cnt + ovf + dtype detect ---------------------------
__global__ __launch_bounds__(TB) void k_init(const void* ei) {
    int i = blockIdx.x * blockDim.x + threadIdx.x;
    if (i < N_NODES) g_cnt[i] = 0;
    if (blockIdx.x == 0) {
        __shared__ int any_nz;
        if (threadIdx.x == 0) { any_nz = 0; g_ovf_cnt = 0; }
        __syncthreads();
        const int* w = (const int*)ei;
        for (int k = threadIdx.x; k < 4096; k += blockDim.x)
            if (w[2 * k + 1] != 0) any_nz = 1;
        __syncthreads();
        if (threadIdx.x == 0) g_is64 = any_nz ? 0 : 1;
    }
}

// ---------------- count + direct bin fill ----------------------------------------
__global__ void k_count_fill(const void* __restrict__ ei) {
    int e = blockIdx.x * blockDim.x + threadIdx.x;
    if (e < N_EDGES) {
        int is64 = g_is64;
        int s, d;
        if (is64) {
            s = (int)((const long long*)ei)[e];
            d = (int)((const long long*)ei)[(long long)N_EDGES + e];
        } else {
            s = ((const int*)ei)[e];
            d = ((const int*)ei)[N_EDGES + e];
        }
        if ((unsigned)d < N_NODES) {
            int r = atomicAdd(&g_cnt[d], 1);
            if (r < CAP) {
                g_bins[d * CAP + r] = s;
            } else {
                int o = atomicAdd(&g_ovf_cnt, 1);
                if (o < OVF_CAP) { g_ovf_d[o] = d; g_ovf_s[o] = s; }
            }
        }
    }
}

// ---------------- gemm1 (warp per node) + dinv ------------------------------------
__global__ __launch_bounds__(TB) void k_gemm1(
    const float* __restrict__ x, const float* __restrict__ W)
{
    __shared__ float2 sW2[34 * 32];   // sW2[k*32+j] = W[k][2j..2j+1]
    for (int i = threadIdx.x; i < 34 * 32; i += blockDim.x) {
        int k = i >> 5, j = i & 31;
        sW2[i] = make_float2(W[k * 64 + 2 * j], W[k * 64 + 2 * j + 1]);
    }
    __syncthreads();
    int warp = blockIdx.x * 8 + (threadIdx.x >> 5);
    int lane = threadIdx.x & 31;
    if (warp >= N_NODES) return;
    const int node = warp;

    const float2* xr = (const float2*)(x + (size_t)node * 34);
    float2 xv = (lane < 17) ? xr[lane] : make_float2(0.f, 0.f);

    float a0 = 0.f, a1 = 0.f;
#pragma unroll
    for (int k = 0; k < 17; k++) {
        float x0 = __shfl_sync(FULLM, xv.x, k);
        float x1 = __shfl_sync(FULLM, xv.y, k);
        float2 w0 = sW2[(2 * k) * 32 + lane];
        float2 w1 = sW2[(2 * k + 1) * 32 + lane];
        a0 += x0 * w0.x + x1 * w1.x;
        a1 += x0 * w0.y + x1 * w1.y;
    }
    float dv = rsqrtf((float)g_cnt[node] + 1.0f);   // +1 self loop
    if (lane == 0) g_dinv[node] = dv;
    ((__half2*)g_H1)[(size_t)node * 32 + lane] =
        __floats2half2_rn(a0 * dv, a1 * dv);
}

// ---------------- F1: aggregate 64d (single 4-deep HADD2/iter) + GEMM 64->32 -----
__global__ __launch_bounds__(256) void k_f1(
    const float* __restrict__ b1, const float* __restrict__ W2)
{
    __shared__ float2 sW[32 * 32];   // sW[k*32+f] = (W2[2k][f], W2[2k+1][f]) 8KB
    for (int i = threadIdx.x; i < 32 * 32; i += blockDim.x) {
        int k = i >> 5, f = i & 31;
        sW[i] = make_float2(W2[(2 * k) * 32 + f], W2[(2 * k + 1) * 32 + f]);
    }
    __syncthreads();

    int warp = (blockIdx.x * blockDim.x + threadIdx.x) >> 5;
    int lane = threadIdx.x & 31;
    if (warp >= N_NODES) return;
    const int node = warp;
    const __half2* t = (const __half2*)g_H1;

    float2 self = __half22float2(t[(size_t)node * 32 + lane]);
    float ax0 = self.x, ay0 = self.y, ax1 = 0.f, ay1 = 0.f;

    int deg = g_cnt[node];
    int m = min(deg, CAP);
    const int* bin = g_bins + node * CAP;
    int e0 = 0;
    for (; e0 + 32 <= m; e0 += 32) {
        int s = bin[e0 + lane];
#pragma unroll
        for (int j = 0; j < 32; j += 4) {        // 4 edges: one 4-deep fp16 tree
            int s0 = __shfl_sync(FULLM, s, j);
            int s1 = __shfl_sync(FULLM, s, j + 1);
            int s2 = __shfl_sync(FULLM, s, j + 2);
            int s3 = __shfl_sync(FULLM, s, j + 3);
            __half2 v0 = t[(size_t)s0 * 32 + lane];
            __half2 v1 = t[(size_t)s1 * 32 + lane];
            __half2 v2 = t[(size_t)s2 * 32 + lane];
            __half2 v3 = t[(size_t)s3 * 32 + lane];
            __half2 u = __hadd2(__hadd2(v0, v1), __hadd2(v2, v3));
            float2 p = __half22float2(u);
            if ((j & 4) == 0) { ax0 += p.x; ay0 += p.y; }
            else              { ax1 += p.x; ay1 += p.y; }
        }
    }
    if (e0 < m) {
        int mm = m - e0;
        int s = (e0 + lane < m) ? bin[e0 + lane] : 0;
        for (int j = 0; j < mm; j++) {
            int sj = __shfl_sync(FULLM, s, j);
            float2 r = __half22float2(t[(size_t)sj * 32 + lane]);
            ax0 += r.x; ay0 += r.y;
        }
    }
    int L = g_ovf_cnt; if (L > OVF_CAP) L = OVF_CAP;
    for (int i = 0; i < L; i++) {
        if (g_ovf_d[i] == node) {
            float2 r = __half22float2(t[(size_t)g_ovf_s[i] * 32 + lane]);
            ax0 += r.x; ay0 += r.y;
        }
    }

    float d = g_dinv[node];
    float2 bv = ((const float2*)b1)[lane];
    float hx = tanhf(d * (ax0 + ax1) + bv.x);   // h1[2*lane]
    float hy = tanhf(d * (ay0 + ay1) + bv.y);   // h1[2*lane+1]

    // GEMM 64->32 (packed float2 weights, shfl broadcast)
    float acc = 0.f;
#pragma unroll
    for (int k = 0; k < 32; k++) {
        float x0 = __shfl_sync(FULLM, hx, k);
        float x1 = __shfl_sync(FULLM, hy, k);
        float2 w = sW[k * 32 + lane];
        acc += x0 * w.x + x1 * w.y;
    }
    g_H2[(size_t)node * 32 + lane] = __float2half(acc * d);
}

// ---------------- F2: aggregate 32d (4-deep HADD2) + GEMM 32->16 -> H3 -----------
__global__ __launch_bounds__(256) void k_f2(
    const float* __restrict__ b2, const float* __restrict__ W3)
{
    __shared__ float sW[32 * 16];
    for (int i = threadIdx.x; i < 32 * 16; i += blockDim.x) sW[i] = W3[i];
    __syncthreads();

    int warp = (blockIdx.x * blockDim.x + threadIdx.x) >> 5;
    int lane = threadIdx.x & 31;
    if (warp >= N_NODES) return;
    const int node = warp;
    const __half2* t = (const __half2*)g_H2;
    int sub = lane >> 4;          // 2 subgroups
    int c   = lane & 15;

    float ax = 0.f, ay = 0.f, bx = 0.f, by = 0.f;
    if (sub == 0) {
        float2 s = __half22float2(t[(size_t)node * 16 + c]);
        ax = s.x; ay = s.y;
    }
    int deg = g_cnt[node];
    int m = min(deg, CAP);
    const int* bin = g_bins + node * CAP;
    int e = sub;
    for (; e + 14 < m; e += 16) {
        int s0 = bin[e];
        int s1 = bin[e + 2];
        int s2 = bin[e + 4];
        int s3 = bin[e + 6];
        int s4 = bin[e + 8];
        int s5 = bin[e + 10];
        int s6 = bin[e + 12];
        int s7 = bin[e + 14];
        __half2 v0 = t[(size_t)s0 * 16 + c];
        __half2 v1 = t[(size_t)s1 * 16 + c];
        __half2 v2 = t[(size_t)s2 * 16 + c];
        __half2 v3 = t[(size_t)s3 * 16 + c];
        __half2 v4 = t[(size_t)s4 * 16 + c];
        __half2 v5 = t[(size_t)s5 * 16 + c];
        __half2 v6 = t[(size_t)s6 * 16 + c];
        __half2 v7 = t[(size_t)s7 * 16 + c];
        __half2 u0 = __hadd2(__hadd2(v0, v1), __hadd2(v2, v3));
        __half2 u1 = __hadd2(__hadd2(v4, v5), __hadd2(v6, v7));
        float2 p0 = __half22float2(u0);
        float2 p1 = __half22float2(u1);
        ax += p0.x; ay += p0.y;
        bx += p1.x; by += p1.y;
    }
    for (; e < m; e += 2) {
        float2 r = __half22float2(t[(size_t)bin[e] * 16 + c]);
        ax += r.x; ay += r.y;
    }
    int L = g_ovf_cnt; if (L > OVF_CAP) L = OVF_CAP;
    for (int i = 0; i < L; i++) {
        if (g_ovf_d[i] == node && (i & 1) == sub) {
            float2 r = __half22float2(t[(size_t)g_ovf_s[i] * 16 + c]);
            ax += r.x; ay += r.y;
        }
    }
    ax += bx; ay += by;
    ax += __shfl_xor_sync(FULLM, ax, 16);
    ay += __shfl_xor_sync(FULLM, ay, 16);

    float d = g_dinv[node];
    float2 bv = ((const float2*)b2)[c];
    float hx = tanhf(d * ax + bv.x);    // h2[2c]
    float hy = tanhf(d * ay + bv.y);    // h2[2c+1]

    // GEMM 32->16: lanes 0..15 compute f = c
    float acc = 0.f;
#pragma unroll
    for (int k = 0; k < 16; k++) {
        float x0 = __shfl_sync(FULLM, hx, k);
        float x1 = __shfl_sync(FULLM, hy, k);
        acc += x0 * sW[(2 * k) * 16 + c] + x1 * sW[(2 * k + 1) * 16 + c];
    }
    if (sub == 0)
        g_H3[(size_t)node * 16 + c] = __float2half(acc * d);
}

// ---------------- F3: aggregate 16d (4-deep HADD2) + GEMM 16->8 -> H4 ------------
__global__ __launch_bounds__(256) void k_f3(
    const float* __restrict__ b3, const float* __restrict__ W4)
{
    __shared__ float sW[16 * 8];
    for (int i = threadIdx.x; i < 16 * 8; i += blockDim.x) sW[i] = W4[i];
    __syncthreads();

    int warp = (blockIdx.x * blockDim.x + threadIdx.x) >> 5;
    int lane = threadIdx.x & 31;
    if (warp >= N_NODES) return;
    const int node = warp;
    const __half2* t = (const __half2*)g_H3;
    int sub = lane >> 3;          // 4 subgroups
    int c   = lane & 7;

    float ax = 0.f, ay = 0.f, bx = 0.f, by = 0.f;
    if (sub == 0) {
        float2 s = __half22float2(t[(size_t)node * 8 + c]);
        ax = s.x; ay = s.y;
    }
    int deg = g_cnt[node];
    int m = min(deg, CAP);
    const int* bin = g_bins + node * CAP;
    int e = sub;
    for (; e + 28 < m; e += 32) {
        int s0 = bin[e];
        int s1 = bin[e + 4];
        int s2 = bin[e + 8];
        int s3 = bin[e + 12];
        int s4 = bin[e + 16];
        int s5 = bin[e + 20];
        int s6 = bin[e + 24];
        int s7 = bin[e + 28];
        __half2 v0 = t[(size_t)s0 * 8 + c];
        __half2 v1 = t[(size_t)s1 * 8 + c];
        __half2 v2 = t[(size_t)s2 * 8 + c];
        __half2 v3 = t[(size_t)s3 * 8 + c];
        __half2 v4 = t[(size_t)s4 * 8 + c];
        __half2 v5 = t[(size_t)s5 * 8 + c];
        __half2 v6 = t[(size_t)s6 * 8 + c];
        __half2 v7 = t[(size_t)s7 * 8 + c];
        __half2 u0 = __hadd2(__hadd2(v0, v1), __hadd2(v2, v3));
        __half2 u1 = __hadd2(__hadd2(v4, v5), __hadd2(v6, v7));
        float2 p0 = __half22float2(u0);
        float2 p1 = __half22float2(u1);
        ax += p0.x; ay += p0.y;
        bx += p1.x; by += p1.y;
    }
    for (; e < m; e += 4) {
        float2 r = __half22float2(t[(size_t)bin[e] * 8 + c]);
        ax += r.x; ay += r.y;
    }
    int L = g_ovf_cnt; if (L > OVF_CAP) L = OVF_CAP;
    for (int i = 0; i < L; i++) {
        if (g_ovf_d[i] == node && (i & 3) == sub) {
            float2 r = __half22float2(t[(size_t)g_ovf_s[i] * 8 + c]);
            ax += r.x; ay += r.y;
        }
    }
    ax += bx; ay += by;
    ax += __shfl_xor_sync(FULLM, ax, 8);
    ay += __shfl_xor_sync(FULLM, ay, 8);
    ax += __shfl_xor_sync(FULLM, ax, 16);
    ay += __shfl_xor_sync(FULLM, ay, 16);

    float d = g_dinv[node];
    float2 bv = ((const float2*)b3)[c];
    float hx = tanhf(d * ax + bv.x);    // h3[2c]
    float hy = tanhf(d * ay + bv.y);

    // GEMM 16->8: lanes 0..7 compute f = c
    float acc = 0.f;
#pragma unroll
    for (int k = 0; k < 8; k++) {
        float x0 = __shfl_sync(FULLM, hx, k);
        float x1 = __shfl_sync(FULLM, hy, k);
        acc += x0 * sW[(2 * k) * 8 + c] + x1 * sW[(2 * k + 1) * 8 + c];
    }
    if (sub == 0)
        g_H4[(size_t)node * 8 + c] = acc * d;
}

// ---------------- F4: aggregate 8d (fp32) + tanh + classifier -> d_out ----------
// d_out: [N*2 logits][N*8 hidden]
__global__ __launch_bounds__(256) void k_f4(
    const float* __restrict__ b4, const float* __restrict__ Wc,
    const float* __restrict__ bc, float* __restrict__ dout)
{
    int warp = (blockIdx.x * blockDim.x + threadIdx.x) >> 5;
    int lane = threadIdx.x & 31;
    if (warp >= N_NODES) return;
    const int node = warp;
    const float2* t = (const float2*)g_H4;
    int sub = lane >> 2;          // 8 subgroups
    int c   = lane & 3;

    float ax = 0.f, ay = 0.f, bx = 0.f, by = 0.f;
    if (sub == 0) {
        float2 s = t[(size_t)node * 4 + c];
        ax = s.x; ay = s.y;
    }
    int deg = g_cnt[node];
    int m = min(deg, CAP);
    const int* bin = g_bins + node * CAP;
    int e = sub;
    for (; e + 24 < m; e += 32) {
        int s0 = bin[e];
        int s1 = bin[e + 8];
        int s2 = bin[e + 16];
        int s3 = bin[e + 24];
        float2 r0 = t[(size_t)s0 * 4 + c];
        float2 r1 = t[(size_t)s1 * 4 + c];
        float2 r2 = t[(size_t)s2 * 4 + c];
        float2 r3 = t[(size_t)s3 * 4 + c];
        ax += r0.x; ay += r0.y;
        bx += r1.x; by += r1.y;
        ax += r2.x; ay += r2.y;
        bx += r3.x; by += r3.y;
    }
    for (; e < m; e += 8) {
        float2 r = t[(size_t)bin[e] * 4 + c];
        ax += r.x; ay += r.y;
    }
    int L = g_ovf_cnt; if (L > OVF_CAP) L = OVF_CAP;
    for (int i = 0; i < L; i++) {
        if (g_ovf_d[i] == node && (i & 7) == sub) {
            float2 r = t[(size_t)g_ovf_s[i] * 4 + c];
            ax += r.x; ay += r.y;
        }
    }
    ax += bx; ay += by;
    ax += __shfl_xor_sync(FULLM, ax, 4);
    ay += __shfl_xor_sync(FULLM, ay, 4);
    ax += __shfl_xor_sync(FULLM, ax, 8);
    ay += __shfl_xor_sync(FULLM, ay, 8);
    ax += __shfl_xor_sync(FULLM, ax, 16);
    ay += __shfl_xor_sync(FULLM, ay, 16);

    float d = g_dinv[node];
    float hx = tanhf(d * ax + b4[2 * c]);      // h4[2c]
    float hy = tanhf(d * ay + b4[2 * c + 1]);  // h4[2c+1]

    float p0 = hx * Wc[(2 * c) * 2 + 0] + hy * Wc[(2 * c + 1) * 2 + 0];
    float p1 = hx * Wc[(2 * c) * 2 + 1] + hy * Wc[(2 * c + 1) * 2 + 1];
    p0 += __shfl_xor_sync(FULLM, p0, 1);
    p1 += __shfl_xor_sync(FULLM, p1, 1);
    p0 += __shfl_xor_sync(FULLM, p0, 2);
    p1 += __shfl_xor_sync(FULLM, p1, 2);

    if (sub == 0) {
        float2* dh = (float2*)(dout + (size_t)2 * N_NODES);
        dh[(size_t)node * 4 + c] = make_float2(hx, hy);
        if (c == 0) {
            dout[(size_t)node * 2 + 0] = p0 + bc[0];
            dout[(size_t)node * 2 + 1] = p1 + bc[1];
        }
    }
}

// ---------------- launcher --------------------------------------------------------
extern "C" void kernel_launch(void* const* d_in, const int* in_sizes, int n_in,
                              void* d_out, int out_size)
{
    const float* x  = (const float*)d_in[0];
    const void*  ei = d_in[1];
    const float* W1 = (const float*)d_in[2];
    const float* b1 = (const float*)d_in[3];
    const float* W2 = (const float*)d_in[4];
    const float* b2 = (const float*)d_in[5];
    const float* W3 = (const float*)d_in[6];
    const float* b3 = (const float*)d_in[7];
    const float* W4 = (const float*)d_in[8];
    const float* b4 = (const float*)d_in[9];
    const float* Wc = (const float*)d_in[10];
    const float* bc = (const float*)d_in[11];
    float* out = (float*)d_out;

    const int nb = (N_NODES + TB - 1) / TB;
    const int wb = (N_NODES * 32 + TB - 1) / TB;  // one warp per node

    k_init<<<nb, TB>>>(ei);            // 0
    k_count_fill<<<EB, TB>>>(ei);      // 1
    k_gemm1<<<G1B, TB>>>(x, W1);       // 2
    k_f1<<<wb, TB>>>(b1, W2);          // 3  (profiled)
    k_f2<<<wb, TB>>>(b2, W3);          // 4
    k_f3<<<wb, TB>>>(b3, W4);          // 5
    k_f4<<<wb, TB>>>(b4, Wc, bc, out); // 6
}

// round 17
// speedup vs baseline: 1.2714x; 1.0274x over previous
#include <cuda_runtime.h>
#include <cuda_fp16.h>
#include <math.h>

#define N_NODES 100000
#define N_EDGES 3200000
#define FULLM 0xffffffffu
#define TB 256
#define EB2 ((N_EDGES / 2 + TB - 1) / TB)             // edge-pair blocks (6250)
#define G1B ((N_NODES + 7) / 8)                       // warp-per-node blocks (12500)
#define CAP 64                                        // bin slots per node
#define OVF_CAP 32768

// ---------------- device scratch ----------------------------------------------
__device__ int    g_is64;
__device__ int    g_cnt[N_NODES];         // zeroed by k_f4 of previous call (or load-init)
__device__ int    g_bins[N_NODES * CAP];  // src ids, bins[d*64 + r]
__device__ int    g_ovf_cnt;
__device__ int    g_ovf_d[OVF_CAP];
__device__ int    g_ovf_s[OVF_CAP];
__device__ float  g_dinv[N_NODES];
__device__ __half g_H1[N_NODES * 64];   // layer-1 gather buf (128B rows)
__device__ __half g_H2[N_NODES * 32];   // layer-2 gather buf (64B rows)
__device__ __half g_H3[N_NODES * 16];   // layer-3 gather buf (32B rows)
__device__ float  g_H4[N_NODES * 8];    // layer-4 gather buf (32B rows, fp32)

// ---------------- init: dtype detect + ovf reset (single tiny block) ------------
__global__ void k_init(const void* ei) {
    __shared__ int any_nz;
    if (threadIdx.x == 0) { any_nz = 0; g_ovf_cnt = 0; }
    __syncthreads();
    const int* w = (const int*)ei;
    for (int k = threadIdx.x; k < 4096; k += blockDim.x)
        if (w[2 * k + 1] != 0) any_nz = 1;
    __syncthreads();
    if (threadIdx.x == 0) g_is64 = any_nz ? 0 : 1;
}

// ---------------- count + direct bin fill (2 edges per thread) -------------------
__device__ __forceinline__ void bin_edge(int s, int d) {
    if ((unsigned)d < N_NODES) {
        int r = atomicAdd(&g_cnt[d], 1);
        if (r < CAP) {
            g_bins[d * CAP + r] = s;
        } else {
            int o = atomicAdd(&g_ovf_cnt, 1);
            if (o < OVF_CAP) { g_ovf_d[o] = d; g_ovf_s[o] = s; }
        }
    }
}

__global__ void k_count_fill(const void* __restrict__ ei) {
    int i = blockIdx.x * blockDim.x + threadIdx.x;   // pair index
    if (i >= N_EDGES / 2) return;
    if (g_is64) {
        longlong2 sv = ((const longlong2*)ei)[i];
        longlong2 dv = ((const longlong2*)((const long long*)ei + N_EDGES))[i];
        bin_edge((int)sv.x, (int)dv.x);
        bin_edge((int)sv.y, (int)dv.y);
    } else {
        int2 sv = ((const int2*)ei)[i];
        int2 dv = ((const int2*)((const int*)ei + N_EDGES))[i];
        bin_edge(sv.x, dv.x);
        bin_edge(sv.y, dv.y);
    }
}

// ---------------- gemm1 (warp per node) + dinv ------------------------------------
__global__ __launch_bounds__(TB) void k_gemm1(
    const float* __restrict__ x, const float* __restrict__ W)
{
    __shared__ float2 sW2[34 * 32];   // sW2[k*32+j] = W[k][2j..2j+1]
    for (int i = threadIdx.x; i < 34 * 32; i += blockDim.x) {
        int k = i >> 5, j = i & 31;
        sW2[i] = make_float2(W[k * 64 + 2 * j], W[k * 64 + 2 * j + 1]);
    }
    __syncthreads();
    int warp = blockIdx.x * 8 + (threadIdx.x >> 5);
    int lane = threadIdx.x & 31;
    if (warp >= N_NODES) return;
    const int node = warp;

    const float2* xr = (const float2*)(x + (size_t)node * 34);
    float2 xv = (lane < 17) ? xr[lane] : make_float2(0.f, 0.f);

    float a0 = 0.f, a1 = 0.f;
#pragma unroll
    for (int k = 0; k < 17; k++) {
        float x0 = __shfl_sync(FULLM, xv.x, k);
        float x1 = __shfl_sync(FULLM, xv.y, k);
        float2 w0 = sW2[(2 * k) * 32 + lane];
        float2 w1 = sW2[(2 * k + 1) * 32 + lane];
        a0 += x0 * w0.x + x1 * w1.x;
        a1 += x0 * w0.y + x1 * w1.y;
    }
    float dv = rsqrtf((float)g_cnt[node] + 1.0f);   // +1 self loop
    if (lane == 0) g_dinv[node] = dv;
    ((__half2*)g_H1)[(size_t)node * 32 + lane] =
        __floats2half2_rn(a0 * dv, a1 * dv);
}

// ---------------- F1: aggregate 64d (4-deep HADD2) + smem-broadcast GEMM ---------
__global__ __launch_bounds__(256) void k_f1(
    const float* __restrict__ b1, const float* __restrict__ W2)
{
    __shared__ float2 sW[32 * 32];   // sW[k*32+f] = (W2[2k][f], W2[2k+1][f]) 8KB
    __shared__ float2 sh[8][32];     // per-warp h pairs: sh[wid][k] = (h[2k], h[2k+1])
    for (int i = threadIdx.x; i < 32 * 32; i += blockDim.x) {
        int k = i >> 5, f = i & 31;
        sW[i] = make_float2(W2[(2 * k) * 32 + f], W2[(2 * k + 1) * 32 + f]);
    }
    __syncthreads();

    int wid  = threadIdx.x >> 5;
    int lane = threadIdx.x & 31;
    int warp = blockIdx.x * 8 + wid;
    if (warp >= N_NODES) return;
    const int node = warp;
    const __half2* t = (const __half2*)g_H1;

    float2 self = __half22float2(t[(size_t)node * 32 + lane]);
    float ax0 = self.x, ay0 = self.y, ax1 = 0.f, ay1 = 0.f;

    int deg = g_cnt[node];
    int m = min(deg, CAP);
    const int* bin = g_bins + node * CAP;
    int e0 = 0;
    for (; e0 + 32 <= m; e0 += 32) {
        int s = bin[e0 + lane];
#pragma unroll
        for (int j = 0; j < 32; j += 4) {        // 4 edges: one 4-deep fp16 tree
            int s0 = __shfl_sync(FULLM, s, j);
            int s1 = __shfl_sync(FULLM, s, j + 1);
            int s2 = __shfl_sync(FULLM, s, j + 2);
            int s3 = __shfl_sync(FULLM, s, j + 3);
            __half2 v0 = t[(size_t)s0 * 32 + lane];
            __half2 v1 = t[(size_t)s1 * 32 + lane];
            __half2 v2 = t[(size_t)s2 * 32 + lane];
            __half2 v3 = t[(size_t)s3 * 32 + lane];
            __half2 u = __hadd2(__hadd2(v0, v1), __hadd2(v2, v3));
            float2 p = __half22float2(u);
            if ((j & 4) == 0) { ax0 += p.x; ay0 += p.y; }
            else              { ax1 += p.x; ay1 += p.y; }
        }
    }
    if (e0 < m) {
        int mm = m - e0;
        int s = (e0 + lane < m) ? bin[e0 + lane] : 0;
        for (int j = 0; j < mm; j++) {
            int sj = __shfl_sync(FULLM, s, j);
            float2 r = __half22float2(t[(size_t)sj * 32 + lane]);
            ax0 += r.x; ay0 += r.y;
        }
    }
    int L = g_ovf_cnt; if (L > OVF_CAP) L = OVF_CAP;
    for (int i = 0; i < L; i++) {
        if (g_ovf_d[i] == node) {
            float2 r = __half22float2(t[(size_t)g_ovf_s[i] * 32 + lane]);
            ax0 += r.x; ay0 += r.y;
        }
    }

    float d = g_dinv[node];
    float2 bv = ((const float2*)b1)[lane];
    float hx = tanhf(d * (ax0 + ax1) + bv.x);   // h1[2*lane]
    float hy = tanhf(d * (ay0 + ay1) + bv.y);   // h1[2*lane+1]

    // GEMM 64->32 via smem broadcast (no shfl): same arithmetic order as before
    sh[wid][lane] = make_float2(hx, hy);
    __syncwarp();
    float acc = 0.f;
#pragma unroll
    for (int k = 0; k < 32; k++) {
        float2 h2 = sh[wid][k];          // broadcast LDS.64
        float2 w  = sW[k * 32 + lane];   // conflict-free LDS.64
        acc += h2.x * w.x + h2.y * w.y;
    }
    g_H2[(size_t)node * 32 + lane] = __float2half(acc * d);
}

// ---------------- F2: aggregate 32d (4-deep HADD2) + GEMM 32->16 -> H3 -----------
__global__ __launch_bounds__(256) void k_f2(
    const float* __restrict__ b2, const float* __restrict__ W3)
{
    __shared__ float sW[32 * 16];
    for (int i = threadIdx.x; i < 32 * 16; i += blockDim.x) sW[i] = W3[i];
    __syncthreads();

    int warp = (blockIdx.x * blockDim.x + threadIdx.x) >> 5;
    int lane = threadIdx.x & 31;
    if (warp >= N_NODES) return;
    const int node = warp;
    const __half2* t = (const __half2*)g_H2;
    int sub = lane >> 4;          // 2 subgroups
    int c   = lane & 15;

    float ax = 0.f, ay = 0.f, bx = 0.f, by = 0.f;
    if (sub == 0) {
        float2 s = __half22float2(t[(size_t)node * 16 + c]);
        ax = s.x; ay = s.y;
    }
    int deg = g_cnt[node];
    int m = min(deg, CAP);
    const int* bin = g_bins + node * CAP;
    int e = sub;
    for (; e + 14 < m; e += 16) {
        int s0 = bin[e];
        int s1 = bin[e + 2];
        int s2 = bin[e + 4];
        int s3 = bin[e + 6];
        int s4 = bin[e + 8];
        int s5 = bin[e + 10];
        int s6 = bin[e + 12];
        int s7 = bin[e + 14];
        __half2 v0 = t[(size_t)s0 * 16 + c];
        __half2 v1 = t[(size_t)s1 * 16 + c];
        __half2 v2 = t[(size_t)s2 * 16 + c];
        __half2 v3 = t[(size_t)s3 * 16 + c];
        __half2 v4 = t[(size_t)s4 * 16 + c];
        __half2 v5 = t[(size_t)s5 * 16 + c];
        __half2 v6 = t[(size_t)s6 * 16 + c];
        __half2 v7 = t[(size_t)s7 * 16 + c];
        __half2 u0 = __hadd2(__hadd2(v0, v1), __hadd2(v2, v3));
        __half2 u1 = __hadd2(__hadd2(v4, v5), __hadd2(v6, v7));
        float2 p0 = __half22float2(u0);
        float2 p1 = __half22float2(u1);
        ax += p0.x; ay += p0.y;
        bx += p1.x; by += p1.y;
    }
    for (; e < m; e += 2) {
        float2 r = __half22float2(t[(size_t)bin[e] * 16 + c]);
        ax += r.x; ay += r.y;
    }
    int L = g_ovf_cnt; if (L > OVF_CAP) L = OVF_CAP;
    for (int i = 0; i < L; i++) {
        if (g_ovf_d[i] == node && (i & 1) == sub) {
            float2 r = __half22float2(t[(size_t)g_ovf_s[i] * 16 + c]);
            ax += r.x; ay += r.y;
        }
    }
    ax += bx; ay += by;
    ax += __shfl_xor_sync(FULLM, ax, 16);
    ay += __shfl_xor_sync(FULLM, ay, 16);

    float d = g_dinv[node];
    float2 bv = ((const float2*)b2)[c];
    float hx = tanhf(d * ax + bv.x);    // h2[2c]
    float hy = tanhf(d * ay + bv.y);    // h2[2c+1]

    // GEMM 32->16: lanes 0..15 compute f = c
    float acc = 0.f;
#pragma unroll
    for (int k = 0; k < 16; k++) {
        float x0 = __shfl_sync(FULLM, hx, k);
        float x1 = __shfl_sync(FULLM, hy, k);
        acc += x0 * sW[(2 * k) * 16 + c] + x1 * sW[(2 * k + 1) * 16 + c];
    }
    if (sub == 0)
        g_H3[(size_t)node * 16 + c] = __float2half(acc * d);
}

// ---------------- F3: aggregate 16d (4-deep HADD2) + GEMM 16->8 -> H4 ------------
__global__ __launch_bounds__(256) void k_f3(
    const float* __restrict__ b3, const float* __restrict__ W4)
{
    __shared__ float sW[16 * 8];
    for (int i = threadIdx.x; i < 16 * 8; i += blockDim.x) sW[i] = W4[i];
    __syncthreads();

    int warp = (blockIdx.x * blockDim.x + threadIdx.x) >> 5;
    int lane = threadIdx.x & 31;
    if (warp >= N_NODES) return;
    const int node = warp;
    const __half2* t = (const __half2*)g_H3;
    int sub = lane >> 3;          // 4 subgroups
    int c   = lane & 7;

    float ax = 0.f, ay = 0.f, bx = 0.f, by = 0.f;
    if (sub == 0) {
        float2 s = __half22float2(t[(size_t)node * 8 + c]);
        ax = s.x; ay = s.y;
    }
    int deg = g_cnt[node];
    int m = min(deg, CAP);
    const int* bin = g_bins + node * CAP;
    int e = sub;
    for (; e + 28 < m; e += 32) {
        int s0 = bin[e];
        int s1 = bin[e + 4];
        int s2 = bin[e + 8];
        int s3 = bin[e + 12];
        int s4 = bin[e + 16];
        int s5 = bin[e + 20];
        int s6 = bin[e + 24];
        int s7 = bin[e + 28];
        __half2 v0 = t[(size_t)s0 * 8 + c];
        __half2 v1 = t[(size_t)s1 * 8 + c];
        __half2 v2 = t[(size_t)s2 * 8 + c];
        __half2 v3 = t[(size_t)s3 * 8 + c];
        __half2 v4 = t[(size_t)s4 * 8 + c];
        __half2 v5 = t[(size_t)s5 * 8 + c];
        __half2 v6 = t[(size_t)s6 * 8 + c];
        __half2 v7 = t[(size_t)s7 * 8 + c];
        __half2 u0 = __hadd2(__hadd2(v0, v1), __hadd2(v2, v3));
        __half2 u1 = __hadd2(__hadd2(v4, v5), __hadd2(v6, v7));
        float2 p0 = __half22float2(u0);
        float2 p1 = __half22float2(u1);
        ax += p0.x; ay += p0.y;
        bx += p1.x; by += p1.y;
    }
    for (; e < m; e += 4) {
        float2 r = __half22float2(t[(size_t)bin[e] * 8 + c]);
        ax += r.x; ay += r.y;
    }
    int L = g_ovf_cnt; if (L > OVF_CAP) L = OVF_CAP;
    for (int i = 0; i < L; i++) {
        if (g_ovf_d[i] == node && (i & 3) == sub) {
            float2 r = __half22float2(t[(size_t)g_ovf_s[i] * 8 + c]);
            ax += r.x; ay += r.y;
        }
    }
    ax += bx; ay += by;
    ax += __shfl_xor_sync(FULLM, ax, 8);
    ay += __shfl_xor_sync(FULLM, ay, 8);
    ax += __shfl_xor_sync(FULLM, ax, 16);
    ay += __shfl_xor_sync(FULLM, ay, 16);

    float d = g_dinv[node];
    float2 bv = ((const float2*)b3)[c];
    float hx = tanhf(d * ax + bv.x);    // h3[2c]
    float hy = tanhf(d * ay + bv.y);

    // GEMM 16->8: lanes 0..7 compute f = c
    float acc = 0.f;
#pragma unroll
    for (int k = 0; k < 8; k++) {
        float x0 = __shfl_sync(FULLM, hx, k);
        float x1 = __shfl_sync(FULLM, hy, k);
        acc += x0 * sW[(2 * k) * 8 + c] + x1 * sW[(2 * k + 1) * 8 + c];
    }
    if (sub == 0)
        g_H4[(size_t)node * 8 + c] = acc * d;
}

// ---------------- F4: aggregate 8d (fp32) + tanh + classifier -> d_out ----------
// d_out: [N*2 logits][N*8 hidden]; also self-cleans g_cnt for the next call
__global__ __launch_bounds__(256) void k_f4(
    const float* __restrict__ b4, const float* __restrict__ Wc,
    const float* __restrict__ bc, float* __restrict__ dout)
{
    int warp = (blockIdx.x * blockDim.x + threadIdx.x) >> 5;
    int lane = threadIdx.x & 31;
    if (warp >= N_NODES) return;
    const int node = warp;
    const float2* t = (const float2*)g_H4;
    int sub = lane >> 2;          // 8 subgroups
    int c   = lane & 3;

    float ax = 0.f, ay = 0.f, bx = 0.f, by = 0.f;
    if (sub == 0) {
        float2 s = t[(size_t)node * 4 + c];
        ax = s.x; ay = s.y;
    }
    int deg = g_cnt[node];
    int m = min(deg, CAP);
    const int* bin = g_bins + node * CAP;
    int e = sub;
    for (; e + 24 < m; e += 32) {
        int s0 = bin[e];
        int s1 = bin[e + 8];
        int s2 = bin[e + 16];
        int s3 = bin[e + 24];
        float2 r0 = t[(size_t)s0 * 4 + c];
        float2 r1 = t[(size_t)s1 * 4 + c];
        float2 r2 = t[(size_t)s2 * 4 + c];
        float2 r3 = t[(size_t)s3 * 4 + c];
        ax += r0.x; ay += r0.y;
        bx += r1.x; by += r1.y;
        ax += r2.x; ay += r2.y;
        bx += r3.x; by += r3.y;
    }
    for (; e < m; e += 8) {
        float2 r = t[(size_t)bin[e] * 4 + c];
        ax += r.x; ay += r.y;
    }
    int L = g_ovf_cnt; if (L > OVF_CAP) L = OVF_CAP;
    for (int i = 0; i < L; i++) {
        if (g_ovf_d[i] == node && (i & 7) == sub) {
            float2 r = t[(size_t)g_ovf_s[i] * 4 + c];
            ax += r.x; ay += r.y;
        }
    }
    ax += bx; ay += by;
    ax += __shfl_xor_sync(FULLM, ax, 4);
    ay += __shfl_xor_sync(FULLM, ay, 4);
    ax += __shfl_xor_sync(FULLM, ax, 8);
    ay += __shfl_xor_sync(FULLM, ay, 8);
    ax += __shfl_xor_sync(FULLM, ax, 16);
    ay += __shfl_xor_sync(FULLM, ay, 16);

    float d = g_dinv[node];
    float hx = tanhf(d * ax + b4[2 * c]);      // h4[2c]
    float hy = tanhf(d * ay + b4[2 * c + 1]);  // h4[2c+1]

    float p0 = hx * Wc[(2 * c) * 2 + 0] + hy * Wc[(2 * c + 1) * 2 + 0];
    float p1 = hx * Wc[(2 * c) * 2 + 1] + hy * Wc[(2 * c + 1) * 2 + 1];
    p0 += __shfl_xor_sync(FULLM, p0, 1);
    p1 += __shfl_xor_sync(FULLM, p1, 1);
    p0 += __shfl_xor_sync(FULLM, p0, 2);
    p1 += __shfl_xor_sync(FULLM, p1, 2);

    if (sub == 0) {
        float2* dh = (float2*)(dout + (size_t)2 * N_NODES);
        dh[(size_t)node * 4 + c] = make_float2(hx, hy);
        if (c == 0) {
            dout[(size_t)node * 2 + 0] = p0 + bc[0];
            dout[(size_t)node * 2 + 1] = p1 + bc[1];
        }
    }
    if (lane == 0) g_cnt[node] = 0;   // self-clean for next call (last reader)
}

// ---------------- launcher --------------------------------------------------------
extern "C" void kernel_launch(void* const* d_in, const int* in_sizes, int n_in,
                              void* d_out, int out_size)
{
    const float* x  = (const float*)d_in[0];
    const void*  ei = d_in[1];
    const float* W1 = (const float*)d_in[2];
    const float* b1 = (const float*)d_in[3];
    const float* W2 = (const float*)d_in[4];
    const float* b2 = (const float*)d_in[5];
    const float* W3 = (const float*)d_in[6];
    const float* b3 = (const float*)d_in[7];
    const float* W4 = (const float*)d_in[8];
    const float* b4 = (const float*)d_in[9];
    const float* Wc = (const float*)d_in[10];
    const float* bc = (const float*)d_in[11];
    float* out = (float*)d_out;

    const int wb = (N_NODES * 32 + TB - 1) / TB;  // one warp per node

    k_init<<<1, 256>>>(ei);            // 0  (detect + ovf reset, tiny)
    k_count_fill<<<EB2, TB>>>(ei);     // 1  (2 edges/thread)
    k_gemm1<<<G1B, TB>>>(x, W1);       // 2
    k_f1<<<G1B, TB>>>(b1, W2);         // 3  (profiled)
    k_f2<<<wb, TB>>>(b2, W3);          // 4
    k_f3<<<wb, TB>>>(b3, W4);          // 5
    k_f4<<<wb, TB>>>(b4, Wc, bc, out); // 6  (self-cleans g_cnt)
}